// round 14
// baseline (speedup 1.0000x reference)
#include <cuda_runtime.h>
#include <cstdint>
#include <cstring>

#define Bx 64
#define Cx 3
#define Hx 384
#define Wx 384
#define PLANE (Hx * Wx)          // 147456
#define IMGS_PER_TEX 16
#define TEX_H (IMGS_PER_TEX * Cx * Hx)   // 18432 rows

// ---- hybrid kernel: TEX + LSU pipes interleaved per-warp via channel split ----
// Row parity alternates channel->pipe assignment: 6 TEX gathers + 6 LDG-quads
// per thread over 4 rows. __launch_bounds__(256,6) caps regs at 42 -> 6
// blocks/SM (48 warps, 75% occ) to hide TEX/LDG latency.
__global__ __launch_bounds__(256, 6) void affine_mix_kernel(
    cudaTextureObject_t t0, cudaTextureObject_t t1,
    cudaTextureObject_t t2, cudaTextureObject_t t3,
    const float* __restrict__ imgs,
    const float* __restrict__ theta,
    float* __restrict__ out)
{
    int lane  = threadIdx.x;          // 0..31
    int w     = threadIdx.y;          // 0..7
    int warpx = w & 3;
    int warpy = w >> 2;

    int x     = blockIdx.x * 128 + warpx * 32 + lane;
    int ybase = blockIdx.y * 8 + warpy * 4;
    int b     = blockIdx.z;

    const float* th = theta + b * 6;
    float t00 = __ldg(th + 0), t01 = __ldg(th + 1), t02 = __ldg(th + 2);
    float t10 = __ldg(th + 3), t11 = __ldg(th + 4), t12 = __ldg(th + 5);

    cudaTextureObject_t tex = (b & 32) ? ((b & 16) ? t3 : t2)
                                       : ((b & 16) ? t1 : t0);
    float rowb = (float)((b & (IMGS_PER_TEX - 1)) * Cx * Hx);

    float xv  = (float)x - 191.5f;
    float ixx = fmaf(xv, t00, t02 + 191.5f);
    float iyx = fmaf(xv, t10, t12 + 191.5f);

    const float* img  = imgs + (size_t)b * (Cx * PLANE);
    float*       outb = out  + (size_t)b * (Cx * PLANE);

#pragma unroll
    for (int r = 0; r < 4; r++) {
        int y = ybase + r;
        float yv = (float)y - 191.5f;
        float ix = fmaf(yv, t01, ixx);
        float iy = fmaf(yv, t11, iyx);

        float fx0 = floorf(ix), fy0 = floorf(iy);

        // ---- issue TEX gathers FIRST (long latency, start early) ----
        float gx = fx0 + 1.0f;
        float gy = rowb + fy0 + 1.0f;

        float4 g0, g1;
        if ((r & 1) == 0) {
            g0 = tex2Dgather<float4>(tex, gx, gy, 0);
            g1 = tex2Dgather<float4>(tex, gx, gy + (float)Hx, 0);
        } else {
            g0 = tex2Dgather<float4>(tex, gx, gy, 0);
        }

        // ---- ALU: weights + clamped LDG addresses overlap TEX latency ----
        float wx1 = ix - fx0,  wy1 = iy - fy0;
        float wx0 = 1.0f - wx1, wy0 = 1.0f - wy1;

        int x0 = (int)fx0, y0 = (int)fy0;
        int x1 = x0 + 1,  y1 = y0 + 1;

        float vty0 = (y0 >= 0 && y0 < Hx) ? wy0 : 0.0f;
        float vty1 = (y1 >= 0 && y1 < Hx) ? wy1 : 0.0f;
        float wt00 = wx0 * vty0, wt10 = wx1 * vty0;
        float wt01 = wx0 * vty1, wt11 = wx1 * vty1;

        float vx0 = (x0 >= 0 && x0 < Wx) ? 1.0f : 0.0f;
        float vx1 = (x1 >= 0 && x1 < Wx) ? 1.0f : 0.0f;
        float wv00 = wt00 * vx0, wv10 = wt10 * vx1;
        float wv01 = wt01 * vx0, wv11 = wt11 * vx1;

        int xc0 = min(max(x0, 0), Wx - 1);
        int xc1 = min(max(x1, 0), Wx - 1);
        int yc0 = min(max(y0, 0), Hx - 1);
        int yc1 = min(max(y1, 0), Hx - 1);

        int o00 = yc0 * Wx + xc0;
        int o10 = yc0 * Wx + xc1;
        int o01 = yc1 * Wx + xc0;
        int o11 = yc1 * Wx + xc1;

        float r0, r1, r2;

        if ((r & 1) == 0) {
            // even rows: ch0, ch1 via TEX (already in flight); ch2 via LDG
            const float* p2 = img + 2 * PLANE;
            float a2 = __ldg(p2 + o00);
            float b2 = __ldg(p2 + o10);
            float c2 = __ldg(p2 + o01);
            float d2 = __ldg(p2 + o11);

            // gather order: .w=(x0,y0) .z=(x1,y0) .x=(x0,y1) .y=(x1,y1)
            r0 = fmaf(wt00, g0.w, fmaf(wt10, g0.z, fmaf(wt01, g0.x, wt11 * g0.y)));
            r1 = fmaf(wt00, g1.w, fmaf(wt10, g1.z, fmaf(wt01, g1.x, wt11 * g1.y)));
            r2 = fmaf(wv00, a2, fmaf(wv10, b2, fmaf(wv01, c2, wv11 * d2)));
        } else {
            // odd rows: ch0 via TEX; ch1, ch2 via LDG
            const float* p1 = img + 1 * PLANE;
            const float* p2 = img + 2 * PLANE;
            float a1 = __ldg(p1 + o00);
            float b1 = __ldg(p1 + o10);
            float c1 = __ldg(p1 + o01);
            float d1 = __ldg(p1 + o11);
            float a2 = __ldg(p2 + o00);
            float b2 = __ldg(p2 + o10);
            float c2 = __ldg(p2 + o01);
            float d2 = __ldg(p2 + o11);

            r0 = fmaf(wt00, g0.w, fmaf(wt10, g0.z, fmaf(wt01, g0.x, wt11 * g0.y)));
            r1 = fmaf(wv00, a1, fmaf(wv10, b1, fmaf(wv01, c1, wv11 * d1)));
            r2 = fmaf(wv00, a2, fmaf(wv10, b2, fmaf(wv01, c2, wv11 * d2)));
        }

        int rowoff = y * Wx + x;
        outb[0 * PLANE + rowoff] = r0;
        outb[1 * PLANE + rowoff] = r1;
        outb[2 * PLANE + rowoff] = r2;
    }
}

// ---------------- fallback: proven R3 global-gather kernel ----------------
__global__ __launch_bounds__(256) void affine_ldg_kernel(
    const float* __restrict__ imgs,
    const float* __restrict__ theta,
    float* __restrict__ out)
{
    int lane  = threadIdx.x;
    int w     = threadIdx.y;
    int warpx = w & 3;
    int warpy = w >> 2;

    int x     = blockIdx.x * 128 + warpx * 32 + lane;
    int ybase = blockIdx.y * 8 + warpy * 4;
    int b     = blockIdx.z;

    const float* th = theta + b * 6;
    float t00 = __ldg(th + 0), t01 = __ldg(th + 1), t02 = __ldg(th + 2);
    float t10 = __ldg(th + 3), t11 = __ldg(th + 4), t12 = __ldg(th + 5);

    float xv  = (float)x - 191.5f;
    float ixx = fmaf(xv, t00, t02 + 191.5f);
    float iyx = fmaf(xv, t10, t12 + 191.5f);

    const float* img  = imgs + (size_t)b * (Cx * PLANE);
    float*       outb = out  + (size_t)b * (Cx * PLANE);

#pragma unroll
    for (int r = 0; r < 4; r++) {
        int y = ybase + r;
        float yv = (float)y - 191.5f;
        float ix = fmaf(yv, t01, ixx);
        float iy = fmaf(yv, t11, iyx);

        float fx0 = floorf(ix), fy0 = floorf(iy);
        float wx1 = ix - fx0,  wy1 = iy - fy0;
        float wx0 = 1.0f - wx1, wy0 = 1.0f - wy1;

        int x0 = (int)fx0, y0 = (int)fy0;
        int x1 = x0 + 1,  y1 = y0 + 1;

        float vx0 = (x0 >= 0 && x0 < Wx) ? 1.0f : 0.0f;
        float vx1 = (x1 >= 0 && x1 < Wx) ? 1.0f : 0.0f;
        float vy0 = (y0 >= 0 && y0 < Hx) ? 1.0f : 0.0f;
        float vy1 = (y1 >= 0 && y1 < Hx) ? 1.0f : 0.0f;

        float w00 = wx0 * wy0 * vx0 * vy0;
        float w10 = wx1 * wy0 * vx1 * vy0;
        float w01 = wx0 * wy1 * vx0 * vy1;
        float w11 = wx1 * wy1 * vx1 * vy1;

        int xc0 = min(max(x0, 0), Wx - 1);
        int xc1 = min(max(x1, 0), Wx - 1);
        int yc0 = min(max(y0, 0), Hx - 1);
        int yc1 = min(max(y1, 0), Hx - 1);

        int o00 = yc0 * Wx + xc0;
        int o10 = yc0 * Wx + xc1;
        int o01 = yc1 * Wx + xc0;
        int o11 = yc1 * Wx + xc1;

        float v00c0 = __ldg(img + 0 * PLANE + o00);
        float v10c0 = __ldg(img + 0 * PLANE + o10);
        float v01c0 = __ldg(img + 0 * PLANE + o01);
        float v11c0 = __ldg(img + 0 * PLANE + o11);
        float v00c1 = __ldg(img + 1 * PLANE + o00);
        float v10c1 = __ldg(img + 1 * PLANE + o10);
        float v01c1 = __ldg(img + 1 * PLANE + o01);
        float v11c1 = __ldg(img + 1 * PLANE + o11);
        float v00c2 = __ldg(img + 2 * PLANE + o00);
        float v10c2 = __ldg(img + 2 * PLANE + o10);
        float v01c2 = __ldg(img + 2 * PLANE + o01);
        float v11c2 = __ldg(img + 2 * PLANE + o11);

        float r0 = fmaf(w00, v00c0, fmaf(w10, v10c0, fmaf(w01, v01c0, w11 * v11c0)));
        float r1 = fmaf(w00, v00c1, fmaf(w10, v10c1, fmaf(w01, v01c1, w11 * v11c1)));
        float r2 = fmaf(w00, v00c2, fmaf(w10, v10c2, fmaf(w01, v01c2, w11 * v11c2)));

        int rowoff = y * Wx + x;
        outb[0 * PLANE + rowoff] = r0;
        outb[1 * PLANE + rowoff] = r1;
        outb[2 * PLANE + rowoff] = r2;
    }
}

extern "C" void kernel_launch(void* const* d_in, const int* in_sizes, int n_in,
                              void* d_out, int out_size)
{
    const float* imgs  = (const float*)d_in[0];
    const float* theta = (const float*)d_in[1];
    float* out = (float*)d_out;

    // One-time texture-object setup OUTSIDE graph capture (proven pattern).
    static cudaTextureObject_t tex[4] = {0, 0, 0, 0};
    static const float* cached_imgs = nullptr;
    static int tex_ok = 0;

    if (cached_imgs != imgs) {
        cudaStreamCaptureStatus cs = cudaStreamCaptureStatusNone;
        cudaStreamIsCapturing(cudaStreamLegacy, &cs);
        if (cs == cudaStreamCaptureStatusNone) {
            int ok = 1;
            for (int g = 0; g < 4 && ok; g++) {
                cudaResourceDesc rd;
                memset(&rd, 0, sizeof(rd));
                rd.resType = cudaResourceTypePitch2D;
                rd.res.pitch2D.devPtr =
                    (void*)(imgs + (size_t)g * IMGS_PER_TEX * Cx * PLANE);
                rd.res.pitch2D.desc = cudaCreateChannelDesc<float>();
                rd.res.pitch2D.width = Wx;
                rd.res.pitch2D.height = TEX_H;
                rd.res.pitch2D.pitchInBytes = Wx * sizeof(float);

                cudaTextureDesc td;
                memset(&td, 0, sizeof(td));
                td.addressMode[0] = cudaAddressModeBorder;  // OOB -> 0
                td.addressMode[1] = cudaAddressModeBorder;
                td.filterMode = cudaFilterModePoint;
                td.readMode = cudaReadModeElementType;
                td.normalizedCoords = 0;

                if (cudaCreateTextureObject(&tex[g], &rd, &td, nullptr)
                    != cudaSuccess) ok = 0;
            }
            tex_ok = ok;
            cached_imgs = imgs;
        }
    }

    dim3 block(32, 8);
    dim3 grid(Wx / 128, Hx / 8, Bx);   // (3, 48, 64)
    if (tex_ok && cached_imgs == imgs) {
        affine_mix_kernel<<<grid, block>>>(tex[0], tex[1], tex[2], tex[3],
                                           imgs, theta, out);
    } else {
        affine_ldg_kernel<<<grid, block>>>(imgs, theta, out);
    }
}

// round 15
// speedup vs baseline: 1.0429x; 1.0429x over previous
#include <cuda_runtime.h>
#include <cstdint>
#include <cstring>

#define Bx 64
#define Cx 3
#define Hx 384
#define Wx 384
#define PLANE (Hx * Wx)          // 147456
#define IMGS_PER_TEX 16
#define TEX_H (IMGS_PER_TEX * Cx * Hx)   // 18432 rows

// Hybrid block-split (R12 base, best so far): even images -> TEX pipe,
// odd images -> LSU pipe. Both paths pair-process 2 rows, issuing ALL
// loads for the pair before consuming (2x MLP). LDG blocks additionally
// take a clamp-free fast path when the block's sample bbox is interior.
__global__ __launch_bounds__(256) void affine_hybrid_kernel(
    cudaTextureObject_t t0, cudaTextureObject_t t1,
    cudaTextureObject_t t2, cudaTextureObject_t t3,
    const float* __restrict__ imgs,
    const float* __restrict__ theta,
    float* __restrict__ out,
    int tex_ok)
{
    int lane  = threadIdx.x;          // 0..31
    int w     = threadIdx.y;          // 0..7
    int warpx = w & 3;
    int warpy = w >> 2;

    int xs    = blockIdx.x * 128;
    int ys    = blockIdx.y * 8;
    int x     = xs + warpx * 32 + lane;
    int ybase = ys + warpy * 4;
    int b     = blockIdx.z;

    const float* th = theta + b * 6;
    float t00 = __ldg(th + 0), t01 = __ldg(th + 1), t02 = __ldg(th + 2);
    float t10 = __ldg(th + 3), t11 = __ldg(th + 4), t12 = __ldg(th + 5);
    float c0x = t02 + 191.5f;
    float c1x = t12 + 191.5f;

    float xv  = (float)x - 191.5f;
    float ixx = fmaf(xv, t00, c0x);
    float iyx = fmaf(xv, t10, c1x);

    float* outb = out + (size_t)b * (Cx * PLANE);

    if (tex_ok && (b & 1) == 0) {
        // ================= TEX path: 2 rows x 3ch = 6 gathers in flight ====
        cudaTextureObject_t tex = (b & 32) ? ((b & 16) ? t3 : t2)
                                           : ((b & 16) ? t1 : t0);
        float rowb = (float)((b & (IMGS_PER_TEX - 1)) * Cx * Hx);

#pragma unroll
        for (int p = 0; p < 2; p++) {
            int ya = ybase + 2 * p;
            int yb = ya + 1;

            float yva = (float)ya - 191.5f;
            float ixa = fmaf(yva, t01, ixx);
            float iya = fmaf(yva, t11, iyx);
            float yvb = (float)yb - 191.5f;
            float ixb = fmaf(yvb, t01, ixx);
            float iyb = fmaf(yvb, t11, iyx);

            float fxa = floorf(ixa), fya = floorf(iya);
            float fxb = floorf(ixb), fyb = floorf(iyb);

            float gxa = fxa + 1.0f, gya = rowb + fya + 1.0f;
            float gxb = fxb + 1.0f, gyb = rowb + fyb + 1.0f;

            // all 6 gathers issued before any consume
            float4 gA0 = tex2Dgather<float4>(tex, gxa, gya, 0);
            float4 gB0 = tex2Dgather<float4>(tex, gxb, gyb, 0);
            float4 gA1 = tex2Dgather<float4>(tex, gxa, gya + (float)Hx, 0);
            float4 gB1 = tex2Dgather<float4>(tex, gxb, gyb + (float)Hx, 0);
            float4 gA2 = tex2Dgather<float4>(tex, gxa, gya + (float)(2 * Hx), 0);
            float4 gB2 = tex2Dgather<float4>(tex, gxb, gyb + (float)(2 * Hx), 0);

            float wxa1 = ixa - fxa, wya1 = iya - fya;
            float wxa0 = 1.0f - wxa1, wya0 = 1.0f - wya1;
            float wxb1 = ixb - fxb, wyb1 = iyb - fyb;
            float wxb0 = 1.0f - wxb1, wyb0 = 1.0f - wyb1;

            int y0a = (int)fya, y1a = y0a + 1;
            int y0b = (int)fyb, y1b = y0b + 1;

            float vya0 = (y0a >= 0 && y0a < Hx) ? wya0 : 0.0f;
            float vya1 = (y1a >= 0 && y1a < Hx) ? wya1 : 0.0f;
            float vyb0 = (y0b >= 0 && y0b < Hx) ? wyb0 : 0.0f;
            float vyb1 = (y1b >= 0 && y1b < Hx) ? wyb1 : 0.0f;

            float a00 = wxa0 * vya0, a10 = wxa1 * vya0;
            float a01 = wxa0 * vya1, a11 = wxa1 * vya1;
            float b00 = wxb0 * vyb0, b10 = wxb1 * vyb0;
            float b01 = wxb0 * vyb1, b11 = wxb1 * vyb1;

            // gather order: .w=(x0,y0) .z=(x1,y0) .x=(x0,y1) .y=(x1,y1)
            float ra0 = fmaf(a00, gA0.w, fmaf(a10, gA0.z, fmaf(a01, gA0.x, a11 * gA0.y)));
            float ra1 = fmaf(a00, gA1.w, fmaf(a10, gA1.z, fmaf(a01, gA1.x, a11 * gA1.y)));
            float ra2 = fmaf(a00, gA2.w, fmaf(a10, gA2.z, fmaf(a01, gA2.x, a11 * gA2.y)));
            float rb0 = fmaf(b00, gB0.w, fmaf(b10, gB0.z, fmaf(b01, gB0.x, b11 * gB0.y)));
            float rb1 = fmaf(b00, gB1.w, fmaf(b10, gB1.z, fmaf(b01, gB1.x, b11 * gB1.y)));
            float rb2 = fmaf(b00, gB2.w, fmaf(b10, gB2.z, fmaf(b01, gB2.x, b11 * gB2.y)));

            int offa = ya * Wx + x;
            int offb = yb * Wx + x;
            outb[0 * PLANE + offa] = ra0;
            outb[1 * PLANE + offa] = ra1;
            outb[2 * PLANE + offa] = ra2;
            outb[0 * PLANE + offb] = rb0;
            outb[1 * PLANE + offb] = rb1;
            outb[2 * PLANE + offb] = rb2;
        }
    } else {
        // ================= LDG path: 2 rows x 12 = 24 LDGs in flight =======
        const float* img = imgs + (size_t)b * (Cx * PLANE);

        // Block-level sample bbox (corner extremes of the linear map over
        // the 128x8 block tile) -> uniform interior/border branch.
        float xl = (float)xs - 191.5f, xh = (float)(xs + 127) - 191.5f;
        float yl = (float)ys - 191.5f, yh = (float)(ys + 7) - 191.5f;
        float e0 = xl * t00, e1 = xh * t00, f0 = yl * t01, f1 = yh * t01;
        float g0 = xl * t10, g1 = xh * t10, h0 = yl * t11, h1 = yh * t11;
        float ixmin = fminf(e0, e1) + fminf(f0, f1) + c0x;
        float ixmax = fmaxf(e0, e1) + fmaxf(f0, f1) + c0x;
        float iymin = fminf(g0, g1) + fminf(h0, h1) + c1x;
        float iymax = fmaxf(g0, g1) + fmaxf(h0, h1) + c1x;
        bool interior = (floorf(ixmin) >= 0.0f) && (floorf(ixmax) + 1.0f <= (float)(Wx - 1))
                     && (floorf(iymin) >= 0.0f) && (floorf(iymax) + 1.0f <= (float)(Hx - 1));

#pragma unroll
        for (int p = 0; p < 2; p++) {
            int ya = ybase + 2 * p;
            int yb = ya + 1;

            float yva = (float)ya - 191.5f;
            float ixa = fmaf(yva, t01, ixx);
            float iya = fmaf(yva, t11, iyx);
            float yvb = (float)yb - 191.5f;
            float ixb = fmaf(yvb, t01, ixx);
            float iyb = fmaf(yvb, t11, iyx);

            float fxa = floorf(ixa), fya = floorf(iya);
            float fxb = floorf(ixb), fyb = floorf(iyb);

            float wxa1 = ixa - fxa, wya1 = iya - fya;
            float wxa0 = 1.0f - wxa1, wya0 = 1.0f - wya1;
            float wxb1 = ixb - fxb, wyb1 = iyb - fyb;
            float wxb0 = 1.0f - wxb1, wyb0 = 1.0f - wyb1;

            float ra0, ra1, ra2, rb0, rb1, rb2;

            if (interior) {
                // no clamps, no validity: valid==1 everywhere (matches ref)
                int oa = (int)fya * Wx + (int)fxa;
                int ob = (int)fyb * Wx + (int)fxb;

                const float* pa0 = img + oa;
                const float* pb0 = img + ob;
                const float* pa1 = pa0 + PLANE;
                const float* pb1 = pb0 + PLANE;
                const float* pa2 = pa1 + PLANE;
                const float* pb2 = pb1 + PLANE;

                // 24 independent loads issued before any consume
                float A00 = __ldg(pa0),          A10 = __ldg(pa0 + 1);
                float A01 = __ldg(pa0 + Wx),     A11 = __ldg(pa0 + Wx + 1);
                float B00 = __ldg(pb0),          B10 = __ldg(pb0 + 1);
                float B01 = __ldg(pb0 + Wx),     B11 = __ldg(pb0 + Wx + 1);
                float C00 = __ldg(pa1),          C10 = __ldg(pa1 + 1);
                float C01 = __ldg(pa1 + Wx),     C11 = __ldg(pa1 + Wx + 1);
                float D00 = __ldg(pb1),          D10 = __ldg(pb1 + 1);
                float D01 = __ldg(pb1 + Wx),     D11 = __ldg(pb1 + Wx + 1);
                float E00 = __ldg(pa2),          E10 = __ldg(pa2 + 1);
                float E01 = __ldg(pa2 + Wx),     E11 = __ldg(pa2 + Wx + 1);
                float F00 = __ldg(pb2),          F10 = __ldg(pb2 + 1);
                float F01 = __ldg(pb2 + Wx),     F11 = __ldg(pb2 + Wx + 1);

                float a00 = wxa0 * wya0, a10 = wxa1 * wya0;
                float a01 = wxa0 * wya1, a11 = wxa1 * wya1;
                float b00 = wxb0 * wyb0, b10 = wxb1 * wyb0;
                float b01 = wxb0 * wyb1, b11 = wxb1 * wyb1;

                ra0 = fmaf(a00, A00, fmaf(a10, A10, fmaf(a01, A01, a11 * A11)));
                rb0 = fmaf(b00, B00, fmaf(b10, B10, fmaf(b01, B01, b11 * B11)));
                ra1 = fmaf(a00, C00, fmaf(a10, C10, fmaf(a01, C01, a11 * C11)));
                rb1 = fmaf(b00, D00, fmaf(b10, D10, fmaf(b01, D01, b11 * D11)));
                ra2 = fmaf(a00, E00, fmaf(a10, E10, fmaf(a01, E01, a11 * E11)));
                rb2 = fmaf(b00, F00, fmaf(b10, F10, fmaf(b01, F01, b11 * F11)));
            } else {
                // border: full clamp + validity (R3-proven logic), row a then b
                int x0a = (int)fxa, y0a = (int)fya, x1a = x0a + 1, y1a = y0a + 1;
                int x0b = (int)fxb, y0b = (int)fyb, x1b = x0b + 1, y1b = y0b + 1;

                float vxa0 = (x0a >= 0 && x0a < Wx) ? 1.0f : 0.0f;
                float vxa1 = (x1a >= 0 && x1a < Wx) ? 1.0f : 0.0f;
                float vya0 = (y0a >= 0 && y0a < Hx) ? 1.0f : 0.0f;
                float vya1 = (y1a >= 0 && y1a < Hx) ? 1.0f : 0.0f;
                float vxb0 = (x0b >= 0 && x0b < Wx) ? 1.0f : 0.0f;
                float vxb1 = (x1b >= 0 && x1b < Wx) ? 1.0f : 0.0f;
                float vyb0 = (y0b >= 0 && y0b < Hx) ? 1.0f : 0.0f;
                float vyb1 = (y1b >= 0 && y1b < Hx) ? 1.0f : 0.0f;

                float a00 = wxa0 * wya0 * vxa0 * vya0;
                float a10 = wxa1 * wya0 * vxa1 * vya0;
                float a01 = wxa0 * wya1 * vxa0 * vya1;
                float a11 = wxa1 * wya1 * vxa1 * vya1;
                float b00 = wxb0 * wyb0 * vxb0 * vyb0;
                float b10 = wxb1 * wyb0 * vxb1 * vyb0;
                float b01 = wxb0 * wyb1 * vxb0 * vyb1;
                float b11 = wxb1 * wyb1 * vxb1 * vyb1;

                int xca0 = min(max(x0a, 0), Wx - 1), xca1 = min(max(x1a, 0), Wx - 1);
                int yca0 = min(max(y0a, 0), Hx - 1), yca1 = min(max(y1a, 0), Hx - 1);
                int xcb0 = min(max(x0b, 0), Wx - 1), xcb1 = min(max(x1b, 0), Wx - 1);
                int ycb0 = min(max(y0b, 0), Hx - 1), ycb1 = min(max(y1b, 0), Hx - 1);

                int oa00 = yca0 * Wx + xca0, oa10 = yca0 * Wx + xca1;
                int oa01 = yca1 * Wx + xca0, oa11 = yca1 * Wx + xca1;
                int ob00 = ycb0 * Wx + xcb0, ob10 = ycb0 * Wx + xcb1;
                int ob01 = ycb1 * Wx + xcb0, ob11 = ycb1 * Wx + xcb1;

                ra0 = fmaf(a00, __ldg(img + oa00), fmaf(a10, __ldg(img + oa10),
                      fmaf(a01, __ldg(img + oa01), a11 * __ldg(img + oa11))));
                ra1 = fmaf(a00, __ldg(img + PLANE + oa00), fmaf(a10, __ldg(img + PLANE + oa10),
                      fmaf(a01, __ldg(img + PLANE + oa01), a11 * __ldg(img + PLANE + oa11))));
                ra2 = fmaf(a00, __ldg(img + 2*PLANE + oa00), fmaf(a10, __ldg(img + 2*PLANE + oa10),
                      fmaf(a01, __ldg(img + 2*PLANE + oa01), a11 * __ldg(img + 2*PLANE + oa11))));
                rb0 = fmaf(b00, __ldg(img + ob00), fmaf(b10, __ldg(img + ob10),
                      fmaf(b01, __ldg(img + ob01), b11 * __ldg(img + ob11))));
                rb1 = fmaf(b00, __ldg(img + PLANE + ob00), fmaf(b10, __ldg(img + PLANE + ob10),
                      fmaf(b01, __ldg(img + PLANE + ob01), b11 * __ldg(img + PLANE + ob11))));
                rb2 = fmaf(b00, __ldg(img + 2*PLANE + ob00), fmaf(b10, __ldg(img + 2*PLANE + ob10),
                      fmaf(b01, __ldg(img + 2*PLANE + ob01), b11 * __ldg(img + 2*PLANE + ob11))));
            }

            int offa = ya * Wx + x;
            int offb = yb * Wx + x;
            outb[0 * PLANE + offa] = ra0;
            outb[1 * PLANE + offa] = ra1;
            outb[2 * PLANE + offa] = ra2;
            outb[0 * PLANE + offb] = rb0;
            outb[1 * PLANE + offb] = rb1;
            outb[2 * PLANE + offb] = rb2;
        }
    }
}

extern "C" void kernel_launch(void* const* d_in, const int* in_sizes, int n_in,
                              void* d_out, int out_size)
{
    const float* imgs  = (const float*)d_in[0];
    const float* theta = (const float*)d_in[1];
    float* out = (float*)d_out;

    // One-time texture-object setup OUTSIDE graph capture (proven pattern).
    static cudaTextureObject_t tex[4] = {0, 0, 0, 0};
    static const float* cached_imgs = nullptr;
    static int tex_ok = 0;

    if (cached_imgs != imgs) {
        cudaStreamCaptureStatus cs = cudaStreamCaptureStatusNone;
        cudaStreamIsCapturing(cudaStreamLegacy, &cs);
        if (cs == cudaStreamCaptureStatusNone) {
            int ok = 1;
            for (int g = 0; g < 4 && ok; g++) {
                cudaResourceDesc rd;
                memset(&rd, 0, sizeof(rd));
                rd.resType = cudaResourceTypePitch2D;
                rd.res.pitch2D.devPtr =
                    (void*)(imgs + (size_t)g * IMGS_PER_TEX * Cx * PLANE);
                rd.res.pitch2D.desc = cudaCreateChannelDesc<float>();
                rd.res.pitch2D.width = Wx;
                rd.res.pitch2D.height = TEX_H;
                rd.res.pitch2D.pitchInBytes = Wx * sizeof(float);

                cudaTextureDesc td;
                memset(&td, 0, sizeof(td));
                td.addressMode[0] = cudaAddressModeBorder;  // OOB -> 0
                td.addressMode[1] = cudaAddressModeBorder;
                td.filterMode = cudaFilterModePoint;
                td.readMode = cudaReadModeElementType;
                td.normalizedCoords = 0;

                if (cudaCreateTextureObject(&tex[g], &rd, &td, nullptr)
                    != cudaSuccess) ok = 0;
            }
            tex_ok = ok;
            cached_imgs = imgs;
        }
    }

    int use_tex = (tex_ok && cached_imgs == imgs) ? 1 : 0;

    dim3 block(32, 8);
    dim3 grid(Wx / 128, Hx / 8, Bx);   // (3, 48, 64)
    affine_hybrid_kernel<<<grid, block>>>(tex[0], tex[1], tex[2], tex[3],
                                          imgs, theta, out, use_tex);
}